// round 7
// baseline (speedup 1.0000x reference)
#include <cuda_runtime.h>
#include <cuda_bf16.h>
#include <math.h>
#include <stdint.h>

#define Nn 1024
#define Bb 32
#define Ll 128
#define Hh 4
#define DE 16
#define KKp 4            // K+1
#define CC  512          // B * D_E columns

// ---------------- scratch (static device globals; no allocs allowed) ----------
__device__ float g_Abase[Nn * Nn];                         // 4 MB
__device__ float g_Q[Hh * Nn * DE];
__device__ float g_K[Hh * Nn * DE];
__device__ __nv_bfloat16 g_Ah[Hh * Nn * Nn];               // A_eff hi (8 MB)
__device__ __nv_bfloat16 g_Al[Hh * Nn * Nn];               // A_eff lo (8 MB)

// transposed layout: [matrix][c=0..511][m=0..1023]
__device__ float         g_Gt [Hh * KKp * CC * Nn];        // 32 MB
__device__ __nv_bfloat16 g_Gth[Hh * KKp * CC * Nn];
__device__ __nv_bfloat16 g_Gtl[Hh * KKp * CC * Nn];
__device__ float         g_P1t [Hh * 3 * CC * Nn];
__device__ __nv_bfloat16 g_P1th[Hh * 3 * CC * Nn];
__device__ __nv_bfloat16 g_P1tl[Hh * 3 * CC * Nn];
__device__ float         g_P2t [Hh * 2 * CC * Nn];
__device__ __nv_bfloat16 g_P2th[Hh * 2 * CC * Nn];
__device__ __nv_bfloat16 g_P2tl[Hh * 2 * CC * Nn];
__device__ float         g_P3t [Hh * CC * Nn];

// ---------------- small PTX helpers -------------------------------------------
__device__ __forceinline__ uint32_t s2u(const void* p) {
    uint32_t a;
    asm("{ .reg .u64 t; cvta.to.shared.u64 t, %1; cvt.u32.u64 %0, t; }"
        : "=r"(a) : "l"(p));
    return a;
}
__device__ __forceinline__ uint32_t lds32(uint32_t a) {
    uint32_t v;
    asm volatile("ld.shared.b32 %0, [%1];" : "=r"(v) : "r"(a));
    return v;
}
__device__ __forceinline__ void cp16(uint32_t s, const void* g) {
    asm volatile("cp.async.cg.shared.global [%0], [%1], 16;"
                 :: "r"(s), "l"(g) : "memory");
}
__device__ __forceinline__ void cp_commit() {
    asm volatile("cp.async.commit_group;" ::: "memory");
}
template<int N> __device__ __forceinline__ void cp_wait() {
    asm volatile("cp.async.wait_group %0;" :: "n"(N) : "memory");
}
__device__ __forceinline__ void mma_bf16(float* c, const uint32_t* a, const uint32_t* b) {
    asm volatile(
        "mma.sync.aligned.m16n8k16.row.col.f32.bf16.bf16.f32 "
        "{%0,%1,%2,%3}, {%4,%5,%6,%7}, {%8,%9}, {%0,%1,%2,%3};"
        : "+f"(c[0]), "+f"(c[1]), "+f"(c[2]), "+f"(c[3])
        : "r"(a[0]), "r"(a[1]), "r"(a[2]), "r"(a[3]), "r"(b[0]), "r"(b[1]));
}

// ---------------- kernel 1: A_base = rowsoftmax(exp(-psi*dist2)) --------------
__global__ __launch_bounds__(256) void abase_kernel(const float* __restrict__ psi_emb,
                                                    const float* __restrict__ psi_s) {
    int i = blockIdx.x;
    int tid = threadIdx.x;
    __shared__ float sv[Nn];
    __shared__ float red[256];
    float pi[DE];
#pragma unroll
    for (int d = 0; d < DE; d++) pi[d] = psi_emb[i * DE + d];
    float psi = psi_s[0];

    float lmax = -1e30f;
    for (int j = tid; j < Nn; j += 256) {
        float s = 0.f;
#pragma unroll
        for (int d = 0; d < DE; d++) {
            float df = pi[d] - psi_emb[j * DE + d];
            s += df * df;
        }
        float v = expf(-psi * s);
        sv[j] = v;
        lmax = fmaxf(lmax, v);
    }
    red[tid] = lmax; __syncthreads();
    for (int s = 128; s > 0; s >>= 1) {
        if (tid < s) red[tid] = fmaxf(red[tid], red[tid + s]);
        __syncthreads();
    }
    float M = red[0]; __syncthreads();

    float lsum = 0.f;
    for (int j = tid; j < Nn; j += 256) {
        float e = expf(sv[j] - M);
        sv[j] = e;
        lsum += e;
    }
    red[tid] = lsum; __syncthreads();
    for (int s = 128; s > 0; s >>= 1) {
        if (tid < s) red[tid] += red[tid + s];
        __syncthreads();
    }
    float inv = 1.f / red[0];
    for (int j = tid; j < Nn; j += 256)
        g_Abase[i * Nn + j] = sv[j] * inv;
}

// ---------------- kernel 2: Q/K projections ----------------------------------
__global__ __launch_bounds__(256) void qk_kernel(const float* __restrict__ psi_emb,
                                                 const float* __restrict__ Wq,
                                                 const float* __restrict__ Wk) {
    int idx = blockIdx.x * 256 + threadIdx.x;
    if (idx >= Hh * Nn * DE) return;
    int m = idx % DE;
    int n = (idx / DE) % Nn;
    int h = idx / (DE * Nn);
    float q = 0.f, k = 0.f;
#pragma unroll
    for (int d = 0; d < DE; d++) {
        float p = psi_emb[n * DE + d];
        q += p * Wq[(d * Hh + h) * DE + m];
        k += p * Wk[(d * Hh + h) * DE + m];
    }
    g_Q[(h * Nn + n) * DE + m] = q;
    g_K[(h * Nn + n) * DE + m] = k;
}

// ---------------- kernel 3: A_eff (bf16 hi/lo split) --------------------------
__global__ __launch_bounds__(256) void aeff_kernel(const float* __restrict__ attn_alpha) {
    int n = blockIdx.x;
    int h = blockIdx.y;
    int tid = threadIdx.x;
    __shared__ float sv[Nn];
    __shared__ float red[256];

    float qn[DE];
#pragma unroll
    for (int d = 0; d < DE; d++) qn[d] = g_Q[(h * Nn + n) * DE + d];

    const float scale = 0.25f;
    float lmax = -1e30f;
    for (int m = tid; m < Nn; m += 256) {
        const float4* kp = (const float4*)&g_K[(h * Nn + m) * DE];
        float s = 0.f;
#pragma unroll
        for (int q4 = 0; q4 < 4; q4++) {
            float4 kv = kp[q4];
            s += qn[q4 * 4 + 0] * kv.x + qn[q4 * 4 + 1] * kv.y +
                 qn[q4 * 4 + 2] * kv.z + qn[q4 * 4 + 3] * kv.w;
        }
        s *= scale;
        sv[m] = s;
        lmax = fmaxf(lmax, s);
    }
    red[tid] = lmax; __syncthreads();
    for (int s = 128; s > 0; s >>= 1) {
        if (tid < s) red[tid] = fmaxf(red[tid], red[tid + s]);
        __syncthreads();
    }
    float M = red[0]; __syncthreads();

    float lsum = 0.f;
    for (int m = tid; m < Nn; m += 256) {
        float e = expf(sv[m] - M);
        sv[m] = e;
        lsum += e;
    }
    red[tid] = lsum; __syncthreads();
    for (int s = 128; s > 0; s >>= 1) {
        if (tid < s) red[tid] += red[tid + s];
        __syncthreads();
    }
    float inv = 1.f / red[0];

    float a = attn_alpha[0];
    float alpha = 1.f / (1.f + expf(-a));
    float oma = 1.f - alpha;
    size_t rowoff = ((size_t)h * Nn + n) * Nn;
    for (int m = tid; m < Nn; m += 256) {
        float v = alpha * g_Abase[n * Nn + m] + oma * sv[m] * inv;
        __nv_bfloat16 hi = __float2bfloat16(v);
        g_Ah[rowoff + m] = hi;
        g_Al[rowoff + m] = __float2bfloat16(v - __bfloat162float(hi));
    }
}

// ---------------- kernel 4: G^T, 128x128 tile, 8x8 microtile ------------------
#define GBK 16
__global__ __launch_bounds__(256) void gemmG_kernel(const float* __restrict__ x,
                                                    const float* __restrict__ Fw) {
    int bb = blockIdx.z;
    int j0 = blockIdx.x * 128;   // 2 blocks over j=(h*16+d)*4+k (256 total)
    int m0 = blockIdx.y * 128;   // 8 blocks over m
    int tid = threadIdx.x;
    int tx = tid % 16, ty = tid / 16;

    __shared__ float As[GBK][132];   // [k][m], padded
    __shared__ float Bs[GBK][132];   // [k][j], padded

    const float* Xb = x + (size_t)bb * Nn * Ll;

    float acc[8][8];                 // [ji][mi]
#pragma unroll
    for (int i = 0; i < 8; i++)
#pragma unroll
        for (int j = 0; j < 8; j++) acc[i][j] = 0.f;

    for (int kt = 0; kt < Ll; kt += GBK) {
#pragma unroll
        for (int p = 0; p < 2; p++) {
            int f = p * 256 + tid;
            int row = f >> 2, c4 = (f & 3) * 4;
            float4 av = *(const float4*)&Xb[(size_t)(m0 + row) * Ll + kt + c4];
            As[c4 + 0][row] = av.x;  As[c4 + 1][row] = av.y;
            As[c4 + 2][row] = av.z;  As[c4 + 3][row] = av.w;
            float4 fv = *(const float4*)&Fw[(size_t)(j0 + row) * Ll + kt + c4];
            Bs[c4 + 0][row] = fv.x;  Bs[c4 + 1][row] = fv.y;
            Bs[c4 + 2][row] = fv.z;  Bs[c4 + 3][row] = fv.w;
        }
        __syncthreads();
#pragma unroll
        for (int l = 0; l < GBK; l++) {
            float4 a0 = *(const float4*)&As[l][tx * 4];
            float4 a1 = *(const float4*)&As[l][64 + tx * 4];
            float4 b0 = *(const float4*)&Bs[l][ty * 4];
            float4 b1 = *(const float4*)&Bs[l][64 + ty * 4];
            float ar[8] = {a0.x, a0.y, a0.z, a0.w, a1.x, a1.y, a1.z, a1.w};
            float br[8] = {b0.x, b0.y, b0.z, b0.w, b1.x, b1.y, b1.z, b1.w};
#pragma unroll
            for (int i = 0; i < 8; i++)
#pragma unroll
                for (int j = 0; j < 8; j++) acc[i][j] += br[i] * ar[j];
        }
        __syncthreads();
    }

#pragma unroll
    for (int i = 0; i < 8; i++) {
        int jj = j0 + ((i < 4) ? (ty * 4 + i) : (64 + ty * 4 + i - 4));
        int k = jj & 3, d = (jj >> 2) & 15, h = jj >> 6;
        size_t rowb = ((size_t)(h * KKp + k) * CC + bb * DE + d) * Nn + m0;
#pragma unroll
        for (int seg = 0; seg < 2; seg++) {
            size_t row = rowb + seg * 64 + tx * 4;
            float v0 = acc[i][seg * 4 + 0], v1 = acc[i][seg * 4 + 1];
            float v2 = acc[i][seg * 4 + 2], v3 = acc[i][seg * 4 + 3];
            *(float4*)&g_Gt[row] = make_float4(v0, v1, v2, v3);
            float vv[4] = {v0, v1, v2, v3};
            __nv_bfloat16 hi[4], lo[4];
#pragma unroll
            for (int q = 0; q < 4; q++) {
                hi[q] = __float2bfloat16(vv[q]);
                lo[q] = __float2bfloat16(vv[q] - __bfloat162float(hi[q]));
            }
            *(uint2*)&g_Gth[row] = *(uint2*)hi;
            *(uint2*)&g_Gtl[row] = *(uint2*)lo;
        }
    }
}

// ---------------- kernel 5: mma.sync bf16x3 batched GEMM ----------------------
// C^T[c0:+256][m0:+128] += (Ah+Al)(1024x1024) @ (Bh+Bl)^T.  K-chunk 32.
#define A_T_BYTES (128 * 80)
#define B_T_BYTES (256 * 80)
#define BUF_BYTES (2 * A_T_BYTES + 2 * B_T_BYTES)    // 61440
#define CH_SMEM   (2 * BUF_BYTES)                     // 122880

__global__ __launch_bounds__(256, 1) void cheb_mma(int level) {
    extern __shared__ char dsm[];
    uint32_t sbase = s2u(dsm);

    int tid = threadIdx.x, wid = tid >> 5, lid = tid & 31;
    int wm = wid & 1, wn = wid >> 1;         // 2 x 4 warp grid
    int g = lid >> 2, t = lid & 3;
    int z = blockIdx.z;

    const __nv_bfloat16 *Ah, *Al, *Bh, *Bl;
    float* Cf; __nv_bfloat16 *Ch = 0, *Cl = 0;
    bool emit_bf16 = true;
    if (level == 1) {
        int h = z / 3, ki = z % 3;
        size_t aoff = (size_t)h * Nn * Nn;
        Ah = g_Ah + aoff; Al = g_Al + aoff;
        size_t boff = (size_t)(h * KKp + ki + 1) * CC * Nn;
        Bh = g_Gth + boff; Bl = g_Gtl + boff;
        size_t ooff = (size_t)(h * 3 + ki) * CC * Nn;
        Cf = g_P1t + ooff; Ch = g_P1th + ooff; Cl = g_P1tl + ooff;
    } else if (level == 2) {
        int h = z / 2, tt = z % 2;
        size_t aoff = (size_t)h * Nn * Nn;
        Ah = g_Ah + aoff; Al = g_Al + aoff;
        size_t boff = (size_t)(h * 3 + tt + 1) * CC * Nn;
        Bh = g_P1th + boff; Bl = g_P1tl + boff;
        size_t ooff = (size_t)(h * 2 + tt) * CC * Nn;
        Cf = g_P2t + ooff; Ch = g_P2th + ooff; Cl = g_P2tl + ooff;
    } else {
        int h = z;
        size_t aoff = (size_t)h * Nn * Nn;
        Ah = g_Ah + aoff; Al = g_Al + aoff;
        size_t boff = (size_t)(h * 2 + 1) * CC * Nn;
        Bh = g_P2th + boff; Bl = g_P2tl + boff;
        Cf = g_P3t + (size_t)h * CC * Nn;
        emit_bf16 = false;                    // P3 only consumed as fp32
    }
    int c0 = blockIdx.x * 256;
    int m0 = blockIdx.y * 128;

    const uint32_t oAh = 0, oAl = A_T_BYTES;
    const uint32_t oBh = 2 * A_T_BYTES, oBl = 2 * A_T_BYTES + B_T_BYTES;

    auto load_chunk = [&](int kt, int buf) {
        uint32_t db = sbase + buf * BUF_BYTES;
        const __nv_bfloat16* aS[2] = { Ah + (size_t)m0 * Nn + kt,
                                       Al + (size_t)m0 * Nn + kt };
        const __nv_bfloat16* bS[2] = { Bh + (size_t)c0 * Nn + kt,
                                       Bl + (size_t)c0 * Nn + kt };
#pragma unroll
        for (int s = 0; s < 2; s++) {
#pragma unroll
            for (int p = 0; p < 2; p++) {          // A: 512 uint4
                int lin = p * 256 + tid;
                int row = lin >> 2, c16 = lin & 3;
                cp16(db + (s ? oAl : oAh) + row * 80 + c16 * 16,
                     aS[s] + (size_t)row * Nn + c16 * 8);
            }
#pragma unroll
            for (int p = 0; p < 4; p++) {          // B: 1024 uint4
                int lin = p * 256 + tid;
                int row = lin >> 2, c16 = lin & 3;
                cp16(db + (s ? oBl : oBh) + row * 80 + c16 * 16,
                     bS[s] + (size_t)row * Nn + c16 * 8);
            }
        }
    };

    float acc[4][8][4];
#pragma unroll
    for (int i = 0; i < 4; i++)
#pragma unroll
        for (int j = 0; j < 8; j++)
#pragma unroll
            for (int q = 0; q < 4; q++) acc[i][j][q] = 0.f;

    load_chunk(0, 0);
    cp_commit();

    for (int kc = 0; kc < 32; kc++) {
        int cur = kc & 1;
        if (kc + 1 < 32) { load_chunk((kc + 1) * 32, cur ^ 1); cp_commit(); }
        if (kc + 1 < 32) cp_wait<1>(); else cp_wait<0>();
        __syncthreads();

        uint32_t db = sbase + cur * BUF_BYTES;
#pragma unroll
        for (int kk = 0; kk < 32; kk += 16) {
            uint32_t colb = (kk + 2 * t) * 2;
            // B fragments (hi + lo), kept for all three passes
            uint32_t bh[8][2], bl[8][2];
            uint32_t bO = (wn * 64 + g) * 80 + colb;
#pragma unroll
            for (int ni = 0; ni < 8; ni++) {
                uint32_t o = bO + ni * 8 * 80;
                bh[ni][0] = lds32(db + oBh + o);
                bh[ni][1] = lds32(db + oBh + o + 16);
                bl[ni][0] = lds32(db + oBl + o);
                bl[ni][1] = lds32(db + oBl + o + 16);
            }
            // A-hi fragments, kept for passes 1-2
            uint32_t ah[4][4];
#pragma unroll
            for (int mi = 0; mi < 4; mi++) {
                uint32_t aO = (wm * 64 + mi * 16 + g) * 80 + colb;
                ah[mi][0] = lds32(db + oAh + aO);
                ah[mi][1] = lds32(db + oAh + aO + 8 * 80);
                ah[mi][2] = lds32(db + oAh + aO + 16);
                ah[mi][3] = lds32(db + oAh + aO + 8 * 80 + 16);
            }
            // pass 1: Ah x Bh  (32 independent MMAs)
#pragma unroll
            for (int mi = 0; mi < 4; mi++)
#pragma unroll
                for (int ni = 0; ni < 8; ni++)
                    mma_bf16(acc[mi][ni], ah[mi], bh[ni]);
            // pass 2: Ah x Bl
#pragma unroll
            for (int mi = 0; mi < 4; mi++)
#pragma unroll
                for (int ni = 0; ni < 8; ni++)
                    mma_bf16(acc[mi][ni], ah[mi], bl[ni]);
            // pass 3: Al x Bh  (A-lo loaded per-mi to cap registers)
#pragma unroll
            for (int mi = 0; mi < 4; mi++) {
                uint32_t aO = (wm * 64 + mi * 16 + g) * 80 + colb;
                uint32_t al[4];
                al[0] = lds32(db + oAl + aO);
                al[1] = lds32(db + oAl + aO + 8 * 80);
                al[2] = lds32(db + oAl + aO + 16);
                al[3] = lds32(db + oAl + aO + 8 * 80 + 16);
#pragma unroll
                for (int ni = 0; ni < 8; ni++)
                    mma_bf16(acc[mi][ni], al, bh[ni]);
            }
        }
        __syncthreads();
    }

    // ---- epilogue: transpose through smem, coalesced fp32 + bf16 hi/lo writes
    float* cs = (float*)dsm;                      // 128 c-rows x 132 floats
#pragma unroll 1
    for (int half = 0; half < 2; half++) {
        __syncthreads();
        if ((wn >> 1) == half) {
            int cb = (wn & 1) * 64;
#pragma unroll
            for (int mi = 0; mi < 4; mi++) {
                int m = wm * 64 + mi * 16 + g;
#pragma unroll
                for (int ni = 0; ni < 8; ni++) {
                    int c = cb + ni * 8 + 2 * t;
                    cs[c * 132 + m]           = acc[mi][ni][0];
                    cs[(c + 1) * 132 + m]     = acc[mi][ni][1];
                    cs[c * 132 + m + 8]       = acc[mi][ni][2];
                    cs[(c + 1) * 132 + m + 8] = acc[mi][ni][3];
                }
            }
        }
        __syncthreads();
#pragma unroll
        for (int it = 0; it < 16; it++) {
            int lin = it * 256 + tid;
            int cr = lin >> 5, mv = lin & 31;
            float4 v = *(float4*)&cs[cr * 132 + mv * 4];
            size_t idx = (size_t)(c0 + half * 128 + cr) * Nn + m0 + mv * 4;
            *(float4*)&Cf[idx] = v;
            if (emit_bf16) {
                float vv[4] = {v.x, v.y, v.z, v.w};
                __nv_bfloat16 hi[4], lo[4];
#pragma unroll
                for (int q = 0; q < 4; q++) {
                    hi[q] = __float2bfloat16(vv[q]);
                    lo[q] = __float2bfloat16(vv[q] - __bfloat162float(hi[q]));
                }
                *(uint2*)&Ch[idx] = *(uint2*)hi;
                *(uint2*)&Cl[idx] = *(uint2*)lo;
            }
        }
    }
}

// ---------------- kernel 6: Chebyshev combine + psi contraction + head mix ----
__global__ __launch_bounds__(256) void final_kernel(const float* __restrict__ psi_emb,
                                                    const float* __restrict__ f_b,
                                                    const float* __restrict__ head_mix,
                                                    float* __restrict__ out) {
    int idx = blockIdx.x * 256 + threadIdx.x;
    int n = idx & (Nn - 1);
    int b = idx >> 10;

    float hm[Hh];
    float mmax = -1e30f;
#pragma unroll
    for (int h = 0; h < Hh; h++) { hm[h] = head_mix[h]; mmax = fmaxf(mmax, hm[h]); }
    float msum = 0.f;
#pragma unroll
    for (int h = 0; h < Hh; h++) { hm[h] = expf(hm[h] - mmax); msum += hm[h]; }
    float minv = 1.f / msum;

    float pe[DE];
#pragma unroll
    for (int d = 0; d < DE; d++) pe[d] = psi_emb[n * DE + d];

    float acc = 0.f;
#pragma unroll
    for (int h = 0; h < Hh; h++) {
        float bf = 0.f;
#pragma unroll
        for (int d = 0; d < DE; d++) bf += pe[d] * f_b[h * DE + d];

        const float* G0  = g_Gt  + ((size_t)(h * KKp + 0) * CC + b * DE) * Nn + n;
        const float* G2  = g_Gt  + ((size_t)(h * KKp + 2) * CC + b * DE) * Nn + n;
        const float* P11 = g_P1t + ((size_t)(h * 3 + 0) * CC + b * DE) * Nn + n;
        const float* P13 = g_P1t + ((size_t)(h * 3 + 2) * CC + b * DE) * Nn + n;
        const float* P22 = g_P2t + ((size_t)(h * 2 + 0) * CC + b * DE) * Nn + n;
        const float* P33 = g_P3t + ((size_t)h * CC + b * DE) * Nn + n;

        float zacc = 0.f;
#pragma unroll
        for (int d = 0; d < DE; d++) {
            size_t o = (size_t)d * Nn;
            float zval = G0[o] + P11[o] + 2.f * P22[o] - G2[o]
                       + 4.f * P33[o] - 3.f * P13[o];
            zacc += pe[d] * zval;
        }
        acc += hm[h] * minv * (zacc + bf);
    }
    out[b * Nn + n] = acc;
}

// ---------------- launcher ----------------------------------------------------
extern "C" void kernel_launch(void* const* d_in, const int* in_sizes, int n_in,
                              void* d_out, int out_size) {
    const float* x          = (const float*)d_in[0];
    const float* psi_emb    = (const float*)d_in[1];
    const float* psi        = (const float*)d_in[2];
    const float* Wq         = (const float*)d_in[3];
    const float* Wk         = (const float*)d_in[4];
    const float* attn_alpha = (const float*)d_in[5];
    const float* Fw         = (const float*)d_in[6];
    const float* fb         = (const float*)d_in[7];
    const float* hmix       = (const float*)d_in[8];
    float* out = (float*)d_out;

    cudaFuncSetAttribute(cheb_mma, cudaFuncAttributeMaxDynamicSharedMemorySize,
                         CH_SMEM);

    abase_kernel<<<Nn, 256>>>(psi_emb, psi);
    qk_kernel<<<(Hh * Nn * DE + 255) / 256, 256>>>(psi_emb, Wq, Wk);
    aeff_kernel<<<dim3(Nn, Hh), 256>>>(attn_alpha);
    gemmG_kernel<<<dim3(2, 8, Bb), 256>>>(x, Fw);
    cheb_mma<<<dim3(CC / 256, Nn / 128, 12), 256, CH_SMEM>>>(1);
    cheb_mma<<<dim3(CC / 256, Nn / 128,  8), 256, CH_SMEM>>>(2);
    cheb_mma<<<dim3(CC / 256, Nn / 128,  4), 256, CH_SMEM>>>(3);
    final_kernel<<<(Bb * Nn) / 256, 256>>>(psi_emb, fb, hmix, out);
}

// round 8
// speedup vs baseline: 1.2432x; 1.2432x over previous
#include <cuda_runtime.h>
#include <cuda_fp16.h>
#include <math.h>
#include <stdint.h>

#define Nn 1024
#define Bb 32
#define Ll 128
#define Hh 4
#define DE 16
#define KKp 4            // K+1
#define CC  512          // B * D_E columns

// ---------------- scratch (static device globals; no allocs allowed) ----------
__device__ float g_Abase[Nn * Nn];                 // 4 MB
__device__ float g_Q[Hh * Nn * DE];
__device__ float g_K[Hh * Nn * DE];
__device__ __half g_Ah[Hh * Nn * Nn];              // A_eff hi (8 MB)
__device__ __half g_Al[Hh * Nn * Nn];              // A_eff lo (8 MB)

// transposed layout: [matrix][c=0..511][m=0..1023]
__device__ float  g_Gt [Hh * KKp * CC * Nn];       // 32 MB
__device__ __half g_Gth[Hh * KKp * CC * Nn];       // 16 MB
__device__ float  g_P1t [Hh * 3 * CC * Nn];
__device__ __half g_P1th[Hh * 3 * CC * Nn];
__device__ float  g_P2t [Hh * 2 * CC * Nn];
__device__ __half g_P2th[Hh * 2 * CC * Nn];
__device__ float  g_P3t [Hh * CC * Nn];

// ---------------- small PTX helpers -------------------------------------------
__device__ __forceinline__ uint32_t s2u(const void* p) {
    uint32_t a;
    asm("{ .reg .u64 t; cvta.to.shared.u64 t, %1; cvt.u32.u64 %0, t; }"
        : "=r"(a) : "l"(p));
    return a;
}
__device__ __forceinline__ uint32_t lds32(uint32_t a) {
    uint32_t v;
    asm volatile("ld.shared.b32 %0, [%1];" : "=r"(v) : "r"(a));
    return v;
}
__device__ __forceinline__ void cp16(uint32_t s, const void* g) {
    asm volatile("cp.async.cg.shared.global [%0], [%1], 16;"
                 :: "r"(s), "l"(g) : "memory");
}
__device__ __forceinline__ void cp_commit() {
    asm volatile("cp.async.commit_group;" ::: "memory");
}
template<int N> __device__ __forceinline__ void cp_wait() {
    asm volatile("cp.async.wait_group %0;" :: "n"(N) : "memory");
}
__device__ __forceinline__ void mma_f16(float* c, const uint32_t* a, const uint32_t* b) {
    asm volatile(
        "mma.sync.aligned.m16n8k16.row.col.f32.f16.f16.f32 "
        "{%0,%1,%2,%3}, {%4,%5,%6,%7}, {%8,%9}, {%0,%1,%2,%3};"
        : "+f"(c[0]), "+f"(c[1]), "+f"(c[2]), "+f"(c[3])
        : "r"(a[0]), "r"(a[1]), "r"(a[2]), "r"(a[3]), "r"(b[0]), "r"(b[1]));
}

// ---------------- kernel 1: A_base = rowsoftmax(exp(-psi*dist2)) --------------
__global__ __launch_bounds__(256) void abase_kernel(const float* __restrict__ psi_emb,
                                                    const float* __restrict__ psi_s) {
    int i = blockIdx.x;
    int tid = threadIdx.x;
    __shared__ float sv[Nn];
    __shared__ float red[256];
    float pi[DE];
#pragma unroll
    for (int d = 0; d < DE; d++) pi[d] = psi_emb[i * DE + d];
    float psi = psi_s[0];

    float lmax = -1e30f;
    for (int j = tid; j < Nn; j += 256) {
        float s = 0.f;
#pragma unroll
        for (int d = 0; d < DE; d++) {
            float df = pi[d] - psi_emb[j * DE + d];
            s += df * df;
        }
        float v = expf(-psi * s);
        sv[j] = v;
        lmax = fmaxf(lmax, v);
    }
    red[tid] = lmax; __syncthreads();
    for (int s = 128; s > 0; s >>= 1) {
        if (tid < s) red[tid] = fmaxf(red[tid], red[tid + s]);
        __syncthreads();
    }
    float M = red[0]; __syncthreads();

    float lsum = 0.f;
    for (int j = tid; j < Nn; j += 256) {
        float e = expf(sv[j] - M);
        sv[j] = e;
        lsum += e;
    }
    red[tid] = lsum; __syncthreads();
    for (int s = 128; s > 0; s >>= 1) {
        if (tid < s) red[tid] += red[tid + s];
        __syncthreads();
    }
    float inv = 1.f / red[0];
    for (int j = tid; j < Nn; j += 256)
        g_Abase[i * Nn + j] = sv[j] * inv;
}

// ---------------- kernel 2: Q/K projections ----------------------------------
__global__ __launch_bounds__(256) void qk_kernel(const float* __restrict__ psi_emb,
                                                 const float* __restrict__ Wq,
                                                 const float* __restrict__ Wk) {
    int idx = blockIdx.x * 256 + threadIdx.x;
    if (idx >= Hh * Nn * DE) return;
    int m = idx % DE;
    int n = (idx / DE) % Nn;
    int h = idx / (DE * Nn);
    float q = 0.f, k = 0.f;
#pragma unroll
    for (int d = 0; d < DE; d++) {
        float p = psi_emb[n * DE + d];
        q += p * Wq[(d * Hh + h) * DE + m];
        k += p * Wk[(d * Hh + h) * DE + m];
    }
    g_Q[(h * Nn + n) * DE + m] = q;
    g_K[(h * Nn + n) * DE + m] = k;
}

// ---------------- kernel 3: A_eff (fp16 hi/lo split) --------------------------
__global__ __launch_bounds__(256) void aeff_kernel(const float* __restrict__ attn_alpha) {
    int n = blockIdx.x;
    int h = blockIdx.y;
    int tid = threadIdx.x;
    __shared__ float sv[Nn];
    __shared__ float red[256];

    float qn[DE];
#pragma unroll
    for (int d = 0; d < DE; d++) qn[d] = g_Q[(h * Nn + n) * DE + d];

    const float scale = 0.25f;
    float lmax = -1e30f;
    for (int m = tid; m < Nn; m += 256) {
        const float4* kp = (const float4*)&g_K[(h * Nn + m) * DE];
        float s = 0.f;
#pragma unroll
        for (int q4 = 0; q4 < 4; q4++) {
            float4 kv = kp[q4];
            s += qn[q4 * 4 + 0] * kv.x + qn[q4 * 4 + 1] * kv.y +
                 qn[q4 * 4 + 2] * kv.z + qn[q4 * 4 + 3] * kv.w;
        }
        s *= scale;
        sv[m] = s;
        lmax = fmaxf(lmax, s);
    }
    red[tid] = lmax; __syncthreads();
    for (int s = 128; s > 0; s >>= 1) {
        if (tid < s) red[tid] = fmaxf(red[tid], red[tid + s]);
        __syncthreads();
    }
    float M = red[0]; __syncthreads();

    float lsum = 0.f;
    for (int m = tid; m < Nn; m += 256) {
        float e = expf(sv[m] - M);
        sv[m] = e;
        lsum += e;
    }
    red[tid] = lsum; __syncthreads();
    for (int s = 128; s > 0; s >>= 1) {
        if (tid < s) red[tid] += red[tid + s];
        __syncthreads();
    }
    float inv = 1.f / red[0];

    float a = attn_alpha[0];
    float alpha = 1.f / (1.f + expf(-a));
    float oma = 1.f - alpha;
    size_t rowoff = ((size_t)h * Nn + n) * Nn;
    for (int m = tid; m < Nn; m += 256) {
        float v = alpha * g_Abase[n * Nn + m] + oma * sv[m] * inv;
        __half hi = __float2half(v);
        g_Ah[rowoff + m] = hi;
        g_Al[rowoff + m] = __float2half(v - __half2float(hi));
    }
}

// ---------------- kernel 4: G^T, 128x128 tile, 8x8 microtile ------------------
#define GBK 16
__global__ __launch_bounds__(256) void gemmG_kernel(const float* __restrict__ x,
                                                    const float* __restrict__ Fw) {
    int bb = blockIdx.z;
    int j0 = blockIdx.x * 128;
    int m0 = blockIdx.y * 128;
    int tid = threadIdx.x;
    int tx = tid % 16, ty = tid / 16;

    __shared__ float As[GBK][132];   // [k][m], padded
    __shared__ float Bs[GBK][132];   // [k][j], padded

    const float* Xb = x + (size_t)bb * Nn * Ll;

    float acc[8][8];                 // [ji][mi]
#pragma unroll
    for (int i = 0; i < 8; i++)
#pragma unroll
        for (int j = 0; j < 8; j++) acc[i][j] = 0.f;

    for (int kt = 0; kt < Ll; kt += GBK) {
#pragma unroll
        for (int p = 0; p < 2; p++) {
            int f = p * 256 + tid;
            int row = f >> 2, c4 = (f & 3) * 4;
            float4 av = *(const float4*)&Xb[(size_t)(m0 + row) * Ll + kt + c4];
            As[c4 + 0][row] = av.x;  As[c4 + 1][row] = av.y;
            As[c4 + 2][row] = av.z;  As[c4 + 3][row] = av.w;
            float4 fv = *(const float4*)&Fw[(size_t)(j0 + row) * Ll + kt + c4];
            Bs[c4 + 0][row] = fv.x;  Bs[c4 + 1][row] = fv.y;
            Bs[c4 + 2][row] = fv.z;  Bs[c4 + 3][row] = fv.w;
        }
        __syncthreads();
#pragma unroll
        for (int l = 0; l < GBK; l++) {
            float4 a0 = *(const float4*)&As[l][tx * 4];
            float4 a1 = *(const float4*)&As[l][64 + tx * 4];
            float4 b0 = *(const float4*)&Bs[l][ty * 4];
            float4 b1 = *(const float4*)&Bs[l][64 + ty * 4];
            float ar[8] = {a0.x, a0.y, a0.z, a0.w, a1.x, a1.y, a1.z, a1.w};
            float br[8] = {b0.x, b0.y, b0.z, b0.w, b1.x, b1.y, b1.z, b1.w};
#pragma unroll
            for (int i = 0; i < 8; i++)
#pragma unroll
                for (int j = 0; j < 8; j++) acc[i][j] += br[i] * ar[j];
        }
        __syncthreads();
    }

#pragma unroll
    for (int i = 0; i < 8; i++) {
        int jj = j0 + ((i < 4) ? (ty * 4 + i) : (64 + ty * 4 + i - 4));
        int k = jj & 3, d = (jj >> 2) & 15, h = jj >> 6;
        size_t rowb = ((size_t)(h * KKp + k) * CC + bb * DE + d) * Nn + m0;
#pragma unroll
        for (int seg = 0; seg < 2; seg++) {
            size_t row = rowb + seg * 64 + tx * 4;
            float v0 = acc[i][seg * 4 + 0], v1 = acc[i][seg * 4 + 1];
            float v2 = acc[i][seg * 4 + 2], v3 = acc[i][seg * 4 + 3];
            *(float4*)&g_Gt[row] = make_float4(v0, v1, v2, v3);
            __half hq[4] = {__float2half(v0), __float2half(v1),
                            __float2half(v2), __float2half(v3)};
            *(uint2*)&g_Gth[row] = *(uint2*)hq;
        }
    }
}

// ---------------- kernel 5: mma.sync fp16x2 batched GEMM ----------------------
// C^T[c0:+256][m0:+128] += (Ah+Al)(1024x1024) @ Bh^T.  K-chunk 32, 4-stage ring.
#define A_T_BYTES (128 * 80)
#define B_T_BYTES (256 * 80)
#define STG_BYTES (2 * A_T_BYTES + B_T_BYTES)        // 40960
#define NSTAGE 4
#define CH_SMEM (NSTAGE * STG_BYTES)                  // 163840

__global__ __launch_bounds__(256, 1) void cheb_mma(int level) {
    extern __shared__ char dsm[];
    uint32_t sbase = s2u(dsm);

    int tid = threadIdx.x, wid = tid >> 5, lid = tid & 31;
    int wm = wid & 1, wn = wid >> 1;         // 2 x 4 warp grid
    int g = lid >> 2, t = lid & 3;
    int z = blockIdx.z;

    const __half *Ah, *Al, *Bh;
    float* Cf; __half *Ch = 0;
    bool emit_h = true;
    if (level == 1) {
        int h = z / 3, ki = z % 3;
        size_t aoff = (size_t)h * Nn * Nn;
        Ah = g_Ah + aoff; Al = g_Al + aoff;
        Bh = g_Gth + (size_t)(h * KKp + ki + 1) * CC * Nn;
        size_t ooff = (size_t)(h * 3 + ki) * CC * Nn;
        Cf = g_P1t + ooff; Ch = g_P1th + ooff;
    } else if (level == 2) {
        int h = z / 2, tt = z % 2;
        size_t aoff = (size_t)h * Nn * Nn;
        Ah = g_Ah + aoff; Al = g_Al + aoff;
        Bh = g_P1th + (size_t)(h * 3 + tt + 1) * CC * Nn;
        size_t ooff = (size_t)(h * 2 + tt) * CC * Nn;
        Cf = g_P2t + ooff; Ch = g_P2th + ooff;
    } else {
        int h = z;
        size_t aoff = (size_t)h * Nn * Nn;
        Ah = g_Ah + aoff; Al = g_Al + aoff;
        Bh = g_P2th + (size_t)(h * 2 + 1) * CC * Nn;
        Cf = g_P3t + (size_t)h * CC * Nn;
        emit_h = false;
    }
    int c0 = blockIdx.x * 256;
    int m0 = blockIdx.y * 128;

    const uint32_t oAh = 0, oAl = A_T_BYTES, oBh = 2 * A_T_BYTES;

    // stage loader: Ah,Al 128 rows x 64B + Bh 256 rows x 64B (80B smem stride)
    auto load_chunk = [&](int kc, int buf) {
        int kt = kc * 32;
        uint32_t db = sbase + buf * STG_BYTES;
        // A: 2 splits x 512 cp16 (each thread 4)
        {
            int row = tid >> 1, c16 = (tid & 1) * 2;   // 2 of 4 16B-segments
#pragma unroll
            for (int q = 0; q < 2; q++) {
                cp16(db + oAh + row * 80 + (c16 + q) * 16,
                     Ah + (size_t)(m0 + row) * Nn + kt + (c16 + q) * 8);
                cp16(db + oAl + row * 80 + (c16 + q) * 16,
                     Al + (size_t)(m0 + row) * Nn + kt + (c16 + q) * 8);
            }
        }
        // B: 1024 cp16 (each thread 4)
#pragma unroll
        for (int p = 0; p < 4; p++) {
            int lin = p * 256 + tid;
            int row = lin >> 2, c16 = lin & 3;
            cp16(db + oBh + row * 80 + c16 * 16,
                 Bh + (size_t)(c0 + row) * Nn + kt + c16 * 8);
        }
        cp_commit();
    };

    float acc[4][8][4];
#pragma unroll
    for (int i = 0; i < 4; i++)
#pragma unroll
        for (int j = 0; j < 8; j++)
#pragma unroll
            for (int q = 0; q < 4; q++) acc[i][j][q] = 0.f;

    load_chunk(0, 0);
    load_chunk(1, 1);
    load_chunk(2, 2);

    for (int kc = 0; kc < 32; kc++) {
        int cur = kc & (NSTAGE - 1);
        if (kc <= 29) cp_wait<2>();
        else if (kc == 30) cp_wait<1>();
        else cp_wait<0>();
        __syncthreads();

        uint32_t db = sbase + cur * STG_BYTES;
#pragma unroll
        for (int kk = 0; kk < 32; kk += 16) {
            uint32_t colb = (kk + 2 * t) * 2;
            uint32_t bh[8][2];
            uint32_t bO = (wn * 64 + g) * 80 + colb;
#pragma unroll
            for (int ni = 0; ni < 8; ni++) {
                uint32_t o = bO + ni * 8 * 80;
                bh[ni][0] = lds32(db + oBh + o);
                bh[ni][1] = lds32(db + oBh + o + 16);
            }
            uint32_t ah[4][4], al[4][4];
#pragma unroll
            for (int mi = 0; mi < 4; mi++) {
                uint32_t aO = (wm * 64 + mi * 16 + g) * 80 + colb;
                ah[mi][0] = lds32(db + oAh + aO);
                ah[mi][1] = lds32(db + oAh + aO + 8 * 80);
                ah[mi][2] = lds32(db + oAh + aO + 16);
                ah[mi][3] = lds32(db + oAh + aO + 8 * 80 + 16);
                al[mi][0] = lds32(db + oAl + aO);
                al[mi][1] = lds32(db + oAl + aO + 8 * 80);
                al[mi][2] = lds32(db + oAl + aO + 16);
                al[mi][3] = lds32(db + oAl + aO + 8 * 80 + 16);
            }
#pragma unroll
            for (int mi = 0; mi < 4; mi++)
#pragma unroll
                for (int ni = 0; ni < 8; ni++)
                    mma_f16(acc[mi][ni], ah[mi], bh[ni]);
#pragma unroll
            for (int mi = 0; mi < 4; mi++)
#pragma unroll
                for (int ni = 0; ni < 8; ni++)
                    mma_f16(acc[mi][ni], al[mi], bh[ni]);
        }
        __syncthreads();
        if (kc + 3 < 32) load_chunk(kc + 3, (kc + 3) & (NSTAGE - 1));
    }

    // ---- epilogue: transpose through smem, coalesced fp32 (+fp16) writes
    float* cs = (float*)dsm;                      // 128 c-rows x 132 floats
#pragma unroll 1
    for (int half = 0; half < 2; half++) {
        __syncthreads();
        if ((wn >> 1) == half) {
            int cb = (wn & 1) * 64;
#pragma unroll
            for (int mi = 0; mi < 4; mi++) {
                int m = wm * 64 + mi * 16 + g;
#pragma unroll
                for (int ni = 0; ni < 8; ni++) {
                    int c = cb + ni * 8 + 2 * t;
                    cs[c * 132 + m]           = acc[mi][ni][0];
                    cs[(c + 1) * 132 + m]     = acc[mi][ni][1];
                    cs[c * 132 + m + 8]       = acc[mi][ni][2];
                    cs[(c + 1) * 132 + m + 8] = acc[mi][ni][3];
                }
            }
        }
        __syncthreads();
#pragma unroll
        for (int it = 0; it < 16; it++) {
            int lin = it * 256 + tid;
            int cr = lin >> 5, mv = lin & 31;
            float4 v = *(float4*)&cs[cr * 132 + mv * 4];
            size_t idx = (size_t)(c0 + half * 128 + cr) * Nn + m0 + mv * 4;
            *(float4*)&Cf[idx] = v;
            if (emit_h) {
                __half hq[4] = {__float2half(v.x), __float2half(v.y),
                                __float2half(v.z), __float2half(v.w)};
                *(uint2*)&Ch[idx] = *(uint2*)hq;
            }
        }
    }
}

// ---------------- kernel 6: Chebyshev combine + psi contraction + head mix ----
__global__ __launch_bounds__(256) void final_kernel(const float* __restrict__ psi_emb,
                                                    const float* __restrict__ f_b,
                                                    const float* __restrict__ head_mix,
                                                    float* __restrict__ out) {
    int idx = blockIdx.x * 256 + threadIdx.x;
    int n = idx & (Nn - 1);
    int b = idx >> 10;

    float hm[Hh];
    float mmax = -1e30f;
#pragma unroll
    for (int h = 0; h < Hh; h++) { hm[h] = head_mix[h]; mmax = fmaxf(mmax, hm[h]); }
    float msum = 0.f;
#pragma unroll
    for (int h = 0; h < Hh; h++) { hm[h] = expf(hm[h] - mmax); msum += hm[h]; }
    float minv = 1.f / msum;

    float pe[DE];
#pragma unroll
    for (int d = 0; d < DE; d++) pe[d] = psi_emb[n * DE + d];

    float acc = 0.f;
#pragma unroll
    for (int h = 0; h < Hh; h++) {
        float bf = 0.f;
#pragma unroll
        for (int d = 0; d < DE; d++) bf += pe[d] * f_b[h * DE + d];

        const float* G0  = g_Gt  + ((size_t)(h * KKp + 0) * CC + b * DE) * Nn + n;
        const float* G2  = g_Gt  + ((size_t)(h * KKp + 2) * CC + b * DE) * Nn + n;
        const float* P11 = g_P1t + ((size_t)(h * 3 + 0) * CC + b * DE) * Nn + n;
        const float* P13 = g_P1t + ((size_t)(h * 3 + 2) * CC + b * DE) * Nn + n;
        const float* P22 = g_P2t + ((size_t)(h * 2 + 0) * CC + b * DE) * Nn + n;
        const float* P33 = g_P3t + ((size_t)h * CC + b * DE) * Nn + n;

        float zacc = 0.f;
#pragma unroll
        for (int d = 0; d < DE; d++) {
            size_t o = (size_t)d * Nn;
            float zval = G0[o] + P11[o] + 2.f * P22[o] - G2[o]
                       + 4.f * P33[o] - 3.f * P13[o];
            zacc += pe[d] * zval;
        }
        acc += hm[h] * minv * (zacc + bf);
    }
    out[b * Nn + n] = acc;
}

// ---------------- launcher ----------------------------------------------------
extern "C" void kernel_launch(void* const* d_in, const int* in_sizes, int n_in,
                              void* d_out, int out_size) {
    const float* x          = (const float*)d_in[0];
    const float* psi_emb    = (const float*)d_in[1];
    const float* psi        = (const float*)d_in[2];
    const float* Wq         = (const float*)d_in[3];
    const float* Wk         = (const float*)d_in[4];
    const float* attn_alpha = (const float*)d_in[5];
    const float* Fw         = (const float*)d_in[6];
    const float* fb         = (const float*)d_in[7];
    const float* hmix       = (const float*)d_in[8];
    float* out = (float*)d_out;

    cudaFuncSetAttribute(cheb_mma, cudaFuncAttributeMaxDynamicSharedMemorySize,
                         CH_SMEM);

    abase_kernel<<<Nn, 256>>>(psi_emb, psi);
    qk_kernel<<<(Hh * Nn * DE + 255) / 256, 256>>>(psi_emb, Wq, Wk);
    aeff_kernel<<<dim3(Nn, Hh), 256>>>(attn_alpha);
    gemmG_kernel<<<dim3(2, 8, Bb), 256>>>(x, Fw);
    cheb_mma<<<dim3(CC / 256, Nn / 128, 12), 256, CH_SMEM>>>(1);
    cheb_mma<<<dim3(CC / 256, Nn / 128,  8), 256, CH_SMEM>>>(2);
    cheb_mma<<<dim3(CC / 256, Nn / 128,  4), 256, CH_SMEM>>>(3);
    final_kernel<<<(Bb * Nn) / 256, 256>>>(psi_emb, fb, hmix, out);
}

// round 9
// speedup vs baseline: 1.7162x; 1.3805x over previous
#include <cuda_runtime.h>
#include <cuda_fp16.h>
#include <math.h>
#include <stdint.h>

#define Nn 1024
#define Bb 32
#define Ll 128
#define Hh 4
#define DE 16
#define KKp 4            // K+1
#define CC  512          // B * D_E columns

// ---------------- scratch (static device globals; no allocs allowed) ----------
__device__ float g_Abase[Nn * Nn];                 // 4 MB
__device__ float g_Q[Hh * Nn * DE];
__device__ float g_K[Hh * Nn * DE];
__device__ __half g_Ah[Hh * Nn * Nn];              // A_eff fp16 (8 MB)

// transposed layout: [matrix][c=0..511][m=0..1023]
__device__ float  g_Gt [Hh * KKp * CC * Nn];       // 32 MB
__device__ __half g_Gth[Hh * KKp * CC * Nn];       // 16 MB
__device__ float  g_P1t [Hh * 3 * CC * Nn];
__device__ __half g_P1th[Hh * 3 * CC * Nn];
__device__ float  g_P2t [Hh * 2 * CC * Nn];
__device__ __half g_P2th[Hh * 2 * CC * Nn];
__device__ float  g_P3t [Hh * CC * Nn];

// ---------------- small PTX helpers -------------------------------------------
__device__ __forceinline__ uint32_t s2u(const void* p) {
    uint32_t a;
    asm("{ .reg .u64 t; cvta.to.shared.u64 t, %1; cvt.u32.u64 %0, t; }"
        : "=r"(a) : "l"(p));
    return a;
}
__device__ __forceinline__ uint32_t lds32(uint32_t a) {
    uint32_t v;
    asm volatile("ld.shared.b32 %0, [%1];" : "=r"(v) : "r"(a));
    return v;
}
__device__ __forceinline__ void cp16(uint32_t s, const void* g) {
    asm volatile("cp.async.cg.shared.global [%0], [%1], 16;"
                 :: "r"(s), "l"(g) : "memory");
}
__device__ __forceinline__ void cp_commit() {
    asm volatile("cp.async.commit_group;" ::: "memory");
}
template<int N> __device__ __forceinline__ void cp_wait() {
    asm volatile("cp.async.wait_group %0;" :: "n"(N) : "memory");
}
__device__ __forceinline__ void mma_f16(float* c, const uint32_t* a, const uint32_t* b) {
    asm volatile(
        "mma.sync.aligned.m16n8k16.row.col.f32.f16.f16.f32 "
        "{%0,%1,%2,%3}, {%4,%5,%6,%7}, {%8,%9}, {%0,%1,%2,%3};"
        : "+f"(c[0]), "+f"(c[1]), "+f"(c[2]), "+f"(c[3])
        : "r"(a[0]), "r"(a[1]), "r"(a[2]), "r"(a[3]), "r"(b[0]), "r"(b[1]));
}

// ---------------- kernel 1: A_base = rowsoftmax(exp(-psi*dist2)) --------------
__global__ __launch_bounds__(256) void abase_kernel(const float* __restrict__ psi_emb,
                                                    const float* __restrict__ psi_s) {
    int i = blockIdx.x;
    int tid = threadIdx.x;
    __shared__ float sv[Nn];
    __shared__ float red[256];
    float pi[DE];
#pragma unroll
    for (int d = 0; d < DE; d++) pi[d] = psi_emb[i * DE + d];
    float psi = psi_s[0];

    float lmax = -1e30f;
    for (int j = tid; j < Nn; j += 256) {
        float s = 0.f;
#pragma unroll
        for (int d = 0; d < DE; d++) {
            float df = pi[d] - psi_emb[j * DE + d];
            s += df * df;
        }
        float v = expf(-psi * s);
        sv[j] = v;
        lmax = fmaxf(lmax, v);
    }
    red[tid] = lmax; __syncthreads();
    for (int s = 128; s > 0; s >>= 1) {
        if (tid < s) red[tid] = fmaxf(red[tid], red[tid + s]);
        __syncthreads();
    }
    float M = red[0]; __syncthreads();

    float lsum = 0.f;
    for (int j = tid; j < Nn; j += 256) {
        float e = expf(sv[j] - M);
        sv[j] = e;
        lsum += e;
    }
    red[tid] = lsum; __syncthreads();
    for (int s = 128; s > 0; s >>= 1) {
        if (tid < s) red[tid] += red[tid + s];
        __syncthreads();
    }
    float inv = 1.f / red[0];
    for (int j = tid; j < Nn; j += 256)
        g_Abase[i * Nn + j] = sv[j] * inv;
}

// ---------------- kernel 2: Q/K projections ----------------------------------
__global__ __launch_bounds__(256) void qk_kernel(const float* __restrict__ psi_emb,
                                                 const float* __restrict__ Wq,
                                                 const float* __restrict__ Wk) {
    int idx = blockIdx.x * 256 + threadIdx.x;
    if (idx >= Hh * Nn * DE) return;
    int m = idx % DE;
    int n = (idx / DE) % Nn;
    int h = idx / (DE * Nn);
    float q = 0.f, k = 0.f;
#pragma unroll
    for (int d = 0; d < DE; d++) {
        float p = psi_emb[n * DE + d];
        q += p * Wq[(d * Hh + h) * DE + m];
        k += p * Wk[(d * Hh + h) * DE + m];
    }
    g_Q[(h * Nn + n) * DE + m] = q;
    g_K[(h * Nn + n) * DE + m] = k;
}

// ---------------- kernel 3: A_eff (single fp16) -------------------------------
__global__ __launch_bounds__(256) void aeff_kernel(const float* __restrict__ attn_alpha) {
    int n = blockIdx.x;
    int h = blockIdx.y;
    int tid = threadIdx.x;
    __shared__ float sv[Nn];
    __shared__ float red[256];

    float qn[DE];
#pragma unroll
    for (int d = 0; d < DE; d++) qn[d] = g_Q[(h * Nn + n) * DE + d];

    const float scale = 0.25f;
    float lmax = -1e30f;
    for (int m = tid; m < Nn; m += 256) {
        const float4* kp = (const float4*)&g_K[(h * Nn + m) * DE];
        float s = 0.f;
#pragma unroll
        for (int q4 = 0; q4 < 4; q4++) {
            float4 kv = kp[q4];
            s += qn[q4 * 4 + 0] * kv.x + qn[q4 * 4 + 1] * kv.y +
                 qn[q4 * 4 + 2] * kv.z + qn[q4 * 4 + 3] * kv.w;
        }
        s *= scale;
        sv[m] = s;
        lmax = fmaxf(lmax, s);
    }
    red[tid] = lmax; __syncthreads();
    for (int s = 128; s > 0; s >>= 1) {
        if (tid < s) red[tid] = fmaxf(red[tid], red[tid + s]);
        __syncthreads();
    }
    float M = red[0]; __syncthreads();

    float lsum = 0.f;
    for (int m = tid; m < Nn; m += 256) {
        float e = expf(sv[m] - M);
        sv[m] = e;
        lsum += e;
    }
    red[tid] = lsum; __syncthreads();
    for (int s = 128; s > 0; s >>= 1) {
        if (tid < s) red[tid] += red[tid + s];
        __syncthreads();
    }
    float inv = 1.f / red[0];

    float a = attn_alpha[0];
    float alpha = 1.f / (1.f + expf(-a));
    float oma = 1.f - alpha;
    size_t rowoff = ((size_t)h * Nn + n) * Nn;
    for (int m = tid; m < Nn; m += 256) {
        float v = alpha * g_Abase[n * Nn + m] + oma * sv[m] * inv;
        g_Ah[rowoff + m] = __float2half(v);
    }
}

// ---------------- kernel 4: G^T, 128x128 tile, 8x8 microtile ------------------
#define GBK 16
__global__ __launch_bounds__(256) void gemmG_kernel(const float* __restrict__ x,
                                                    const float* __restrict__ Fw) {
    int bb = blockIdx.z;
    int j0 = blockIdx.x * 128;
    int m0 = blockIdx.y * 128;
    int tid = threadIdx.x;
    int tx = tid % 16, ty = tid / 16;

    __shared__ float As[GBK][132];   // [k][m], padded
    __shared__ float Bs[GBK][132];   // [k][j], padded

    const float* Xb = x + (size_t)bb * Nn * Ll;

    float acc[8][8];                 // [ji][mi]
#pragma unroll
    for (int i = 0; i < 8; i++)
#pragma unroll
        for (int j = 0; j < 8; j++) acc[i][j] = 0.f;

    for (int kt = 0; kt < Ll; kt += GBK) {
#pragma unroll
        for (int p = 0; p < 2; p++) {
            int f = p * 256 + tid;
            int row = f >> 2, c4 = (f & 3) * 4;
            float4 av = *(const float4*)&Xb[(size_t)(m0 + row) * Ll + kt + c4];
            As[c4 + 0][row] = av.x;  As[c4 + 1][row] = av.y;
            As[c4 + 2][row] = av.z;  As[c4 + 3][row] = av.w;
            float4 fv = *(const float4*)&Fw[(size_t)(j0 + row) * Ll + kt + c4];
            Bs[c4 + 0][row] = fv.x;  Bs[c4 + 1][row] = fv.y;
            Bs[c4 + 2][row] = fv.z;  Bs[c4 + 3][row] = fv.w;
        }
        __syncthreads();
#pragma unroll
        for (int l = 0; l < GBK; l++) {
            float4 a0 = *(const float4*)&As[l][tx * 4];
            float4 a1 = *(const float4*)&As[l][64 + tx * 4];
            float4 b0 = *(const float4*)&Bs[l][ty * 4];
            float4 b1 = *(const float4*)&Bs[l][64 + ty * 4];
            float ar[8] = {a0.x, a0.y, a0.z, a0.w, a1.x, a1.y, a1.z, a1.w};
            float br[8] = {b0.x, b0.y, b0.z, b0.w, b1.x, b1.y, b1.z, b1.w};
#pragma unroll
            for (int i = 0; i < 8; i++)
#pragma unroll
                for (int j = 0; j < 8; j++) acc[i][j] += br[i] * ar[j];
        }
        __syncthreads();
    }

#pragma unroll
    for (int i = 0; i < 8; i++) {
        int jj = j0 + ((i < 4) ? (ty * 4 + i) : (64 + ty * 4 + i - 4));
        int k = jj & 3, d = (jj >> 2) & 15, h = jj >> 6;
        size_t rowb = ((size_t)(h * KKp + k) * CC + bb * DE + d) * Nn + m0;
#pragma unroll
        for (int seg = 0; seg < 2; seg++) {
            size_t row = rowb + seg * 64 + tx * 4;
            float v0 = acc[i][seg * 4 + 0], v1 = acc[i][seg * 4 + 1];
            float v2 = acc[i][seg * 4 + 2], v3 = acc[i][seg * 4 + 3];
            *(float4*)&g_Gt[row] = make_float4(v0, v1, v2, v3);
            __half hq[4] = {__float2half(v0), __float2half(v1),
                            __float2half(v2), __float2half(v3)};
            *(uint2*)&g_Gth[row] = *(uint2*)hq;
        }
    }
}

// ---------------- kernel 5: mma.sync fp16 batched GEMM ------------------------
// C^T[c0:+128][m0:+128] = Ah(1024x1024) @ Bh^T.  K-chunk 32, 4-stage, 2 CTA/SM.
#define A_T_BYTES (128 * 80)
#define STG_BYTES (2 * A_T_BYTES)                    // 20480 (A + B)
#define NSTAGE 4
#define CH_SMEM (NSTAGE * STG_BYTES)                 // 81920

__global__ __launch_bounds__(256, 2) void cheb_mma(int level) {
    extern __shared__ char dsm[];
    uint32_t sbase = s2u(dsm);

    int tid = threadIdx.x, wid = tid >> 5, lid = tid & 31;
    int wm = wid & 1, wn = wid >> 1;         // 2(m) x 4(c) warp grid
    int g = lid >> 2, t = lid & 3;
    int z = blockIdx.z;

    const __half *Ah, *Bh;
    float* Cf; __half *Ch = 0;
    bool emit_h = true;
    if (level == 1) {
        int h = z / 3, ki = z % 3;
        Ah = g_Ah + (size_t)h * Nn * Nn;
        Bh = g_Gth + (size_t)(h * KKp + ki + 1) * CC * Nn;
        size_t ooff = (size_t)(h * 3 + ki) * CC * Nn;
        Cf = g_P1t + ooff; Ch = g_P1th + ooff;
    } else if (level == 2) {
        int h = z / 2, tt = z % 2;
        Ah = g_Ah + (size_t)h * Nn * Nn;
        Bh = g_P1th + (size_t)(h * 3 + tt + 1) * CC * Nn;
        size_t ooff = (size_t)(h * 2 + tt) * CC * Nn;
        Cf = g_P2t + ooff; Ch = g_P2th + ooff;
    } else {
        int h = z;
        Ah = g_Ah + (size_t)h * Nn * Nn;
        Bh = g_P2th + (size_t)(h * 2 + 1) * CC * Nn;
        Cf = g_P3t + (size_t)h * CC * Nn;
        emit_h = false;
    }
    int c0 = blockIdx.x * 128;
    int m0 = blockIdx.y * 128;

    const uint32_t oB = A_T_BYTES;

    // stage: A 128 rows x 64B + B 128 rows x 64B, 80B smem stride
    auto load_chunk = [&](int kc, int buf) {
        int kt = kc * 32;
        uint32_t db = sbase + buf * STG_BYTES;
#pragma unroll
        for (int q = 0; q < 2; q++) {
            int lin = q * 256 + tid;
            int row = lin >> 2, c16 = lin & 3;
            cp16(db + row * 80 + c16 * 16,
                 Ah + (size_t)(m0 + row) * Nn + kt + c16 * 8);
            cp16(db + oB + row * 80 + c16 * 16,
                 Bh + (size_t)(c0 + row) * Nn + kt + c16 * 8);
        }
        cp_commit();
    };

    float acc[4][4][4];
#pragma unroll
    for (int i = 0; i < 4; i++)
#pragma unroll
        for (int j = 0; j < 4; j++)
#pragma unroll
            for (int q = 0; q < 4; q++) acc[i][j][q] = 0.f;

    load_chunk(0, 0);
    load_chunk(1, 1);
    load_chunk(2, 2);

    for (int kc = 0; kc < 32; kc++) {
        int cur = kc & (NSTAGE - 1);
        if (kc <= 29) cp_wait<2>();
        else if (kc == 30) cp_wait<1>();
        else cp_wait<0>();
        __syncthreads();

        uint32_t db = sbase + cur * STG_BYTES;
#pragma unroll
        for (int kk = 0; kk < 32; kk += 16) {
            uint32_t colb = (kk + 2 * t) * 2;
            uint32_t bh[4][2];
            uint32_t bO = (wn * 32 + g) * 80 + colb;
#pragma unroll
            for (int ni = 0; ni < 4; ni++) {
                uint32_t o = bO + ni * 8 * 80;
                bh[ni][0] = lds32(db + oB + o);
                bh[ni][1] = lds32(db + oB + o + 16);
            }
            uint32_t ah[4][4];
#pragma unroll
            for (int mi = 0; mi < 4; mi++) {
                uint32_t aO = (wm * 64 + mi * 16 + g) * 80 + colb;
                ah[mi][0] = lds32(db + aO);
                ah[mi][1] = lds32(db + aO + 8 * 80);
                ah[mi][2] = lds32(db + aO + 16);
                ah[mi][3] = lds32(db + aO + 8 * 80 + 16);
            }
#pragma unroll
            for (int mi = 0; mi < 4; mi++)
#pragma unroll
                for (int ni = 0; ni < 4; ni++)
                    mma_f16(acc[mi][ni], ah[mi], bh[ni]);
        }
        __syncthreads();
        if (kc + 3 < 32) load_chunk(kc + 3, (kc + 3) & (NSTAGE - 1));
    }

    // ---- epilogue: transpose through smem, coalesced fp32 (+fp16) writes
    float* cs = (float*)dsm;                      // 128 c-rows x 132 floats
#pragma unroll
    for (int mi = 0; mi < 4; mi++) {
        int m = wm * 64 + mi * 16 + g;
#pragma unroll
        for (int ni = 0; ni < 4; ni++) {
            int c = wn * 32 + ni * 8 + 2 * t;
            cs[c * 132 + m]           = acc[mi][ni][0];
            cs[(c + 1) * 132 + m]     = acc[mi][ni][1];
            cs[c * 132 + m + 8]       = acc[mi][ni][2];
            cs[(c + 1) * 132 + m + 8] = acc[mi][ni][3];
        }
    }
    __syncthreads();
#pragma unroll
    for (int it = 0; it < 16; it++) {
        int lin = it * 256 + tid;
        int cr = lin >> 5, mv = lin & 31;
        float4 v = *(float4*)&cs[cr * 132 + mv * 4];
        size_t idx = (size_t)(c0 + cr) * Nn + m0 + mv * 4;
        *(float4*)&Cf[idx] = v;
        if (emit_h) {
            __half hq[4] = {__float2half(v.x), __float2half(v.y),
                            __float2half(v.z), __float2half(v.w)};
            *(uint2*)&Ch[idx] = *(uint2*)hq;
        }
    }
}

// ---------------- kernel 6: Chebyshev combine + psi contraction + head mix ----
__global__ __launch_bounds__(256) void final_kernel(const float* __restrict__ psi_emb,
                                                    const float* __restrict__ f_b,
                                                    const float* __restrict__ head_mix,
                                                    float* __restrict__ out) {
    int idx = blockIdx.x * 256 + threadIdx.x;
    int n = idx & (Nn - 1);
    int b = idx >> 10;

    float hm[Hh];
    float mmax = -1e30f;
#pragma unroll
    for (int h = 0; h < Hh; h++) { hm[h] = head_mix[h]; mmax = fmaxf(mmax, hm[h]); }
    float msum = 0.f;
#pragma unroll
    for (int h = 0; h < Hh; h++) { hm[h] = expf(hm[h] - mmax); msum += hm[h]; }
    float minv = 1.f / msum;

    float pe[DE];
#pragma unroll
    for (int d = 0; d < DE; d++) pe[d] = psi_emb[n * DE + d];

    float acc = 0.f;
#pragma unroll
    for (int h = 0; h < Hh; h++) {
        float bf = 0.f;
#pragma unroll
        for (int d = 0; d < DE; d++) bf += pe[d] * f_b[h * DE + d];

        const float* G0  = g_Gt  + ((size_t)(h * KKp + 0) * CC + b * DE) * Nn + n;
        const float* G2  = g_Gt  + ((size_t)(h * KKp + 2) * CC + b * DE) * Nn + n;
        const float* P11 = g_P1t + ((size_t)(h * 3 + 0) * CC + b * DE) * Nn + n;
        const float* P13 = g_P1t + ((size_t)(h * 3 + 2) * CC + b * DE) * Nn + n;
        const float* P22 = g_P2t + ((size_t)(h * 2 + 0) * CC + b * DE) * Nn + n;
        const float* P33 = g_P3t + ((size_t)h * CC + b * DE) * Nn + n;

        float zacc = 0.f;
#pragma unroll
        for (int d = 0; d < DE; d++) {
            size_t o = (size_t)d * Nn;
            float zval = G0[o] + P11[o] + 2.f * P22[o] - G2[o]
                       + 4.f * P33[o] - 3.f * P13[o];
            zacc += pe[d] * zval;
        }
        acc += hm[h] * minv * (zacc + bf);
    }
    out[b * Nn + n] = acc;
}

// ---------------- launcher ----------------------------------------------------
extern "C" void kernel_launch(void* const* d_in, const int* in_sizes, int n_in,
                              void* d_out, int out_size) {
    const float* x          = (const float*)d_in[0];
    const float* psi_emb    = (const float*)d_in[1];
    const float* psi        = (const float*)d_in[2];
    const float* Wq         = (const float*)d_in[3];
    const float* Wk         = (const float*)d_in[4];
    const float* attn_alpha = (const float*)d_in[5];
    const float* Fw         = (const float*)d_in[6];
    const float* fb         = (const float*)d_in[7];
    const float* hmix       = (const float*)d_in[8];
    float* out = (float*)d_out;

    cudaFuncSetAttribute(cheb_mma, cudaFuncAttributeMaxDynamicSharedMemorySize,
                         CH_SMEM);

    abase_kernel<<<Nn, 256>>>(psi_emb, psi);
    qk_kernel<<<(Hh * Nn * DE + 255) / 256, 256>>>(psi_emb, Wq, Wk);
    aeff_kernel<<<dim3(Nn, Hh), 256>>>(attn_alpha);
    gemmG_kernel<<<dim3(2, 8, Bb), 256>>>(x, Fw);
    cheb_mma<<<dim3(4, 8, 12), 256, CH_SMEM>>>(1);
    cheb_mma<<<dim3(4, 8,  8), 256, CH_SMEM>>>(2);
    cheb_mma<<<dim3(4, 8,  4), 256, CH_SMEM>>>(3);
    final_kernel<<<(Bb * Nn) / 256, 256>>>(psi_emb, fb, hmix, out);
}